// round 1
// baseline (speedup 1.0000x reference)
#include <cuda_runtime.h>

typedef unsigned long long u64;

__device__ __forceinline__ u64 fma2(u64 a, u64 b, u64 c) {
    u64 d; asm("fma.rn.f32x2 %0, %1, %2, %3;" : "=l"(d) : "l"(a), "l"(b), "l"(c)); return d;
}
__device__ __forceinline__ u64 add2(u64 a, u64 b) {
    u64 d; asm("add.rn.f32x2 %0, %1, %2;" : "=l"(d) : "l"(a), "l"(b)); return d;
}
__device__ __forceinline__ u64 pack2(float lo, float hi) {
    u64 d; asm("mov.b64 %0, {%1, %2};" : "=l"(d) : "f"(lo), "f"(hi)); return d;
}
__device__ __forceinline__ float2 unpack2(u64 v) {
    float2 r; asm("mov.b64 {%0, %1}, %2;" : "=f"(r.x), "=f"(r.y) : "l"(v)); return r;
}

// Scratch for the hidden state h [8192 x 1024] (no cudaMalloc allowed).
__device__ float g_h[8192 * 1024];

// ---------------------------------------------------------------------------
// Kernel 1: h = x @ W1^T + b1      x:[8192,784]  W1:[1024,784]  (both K-major)
// 128x128 tile, BK=16, 256 threads, 8x8 microtile, f32x2 accumulation.
// ---------------------------------------------------------------------------
__global__ void __launch_bounds__(256, 2) sgemm1_kernel(
    const float* __restrict__ A, const float* __restrict__ W,
    const float* __restrict__ bias)
{
    const int K = 784;
    __shared__ float As[16][132];
    __shared__ float Bs[16][132];

    const int tid = threadIdx.x;
    const int bm = blockIdx.y * 128;
    const int bn = blockIdx.x * 128;
    const int tx = tid & 15;        // 0..15 (n)
    const int ty = tid >> 4;        // 0..15 (m)
    const int lm = tid >> 2;        // 0..63 loader row
    const int lk = (tid & 3) * 4;   // k offset within tile

    const float* Ag = A + (size_t)(bm + lm) * K + lk;
    const float* Wg = W + (size_t)(bn + lm) * K + lk;

    u64 c2[8][4];
#pragma unroll
    for (int i = 0; i < 8; i++)
#pragma unroll
        for (int j = 0; j < 4; j++) c2[i][j] = 0ull;

    // prefetch tile 0
    float4 a0 = *(const float4*)(Ag);
    float4 a1 = *(const float4*)(Ag + 64 * K);
    float4 b0 = *(const float4*)(Wg);
    float4 b1 = *(const float4*)(Wg + 64 * K);

#pragma unroll 1
    for (int k0 = 0; k0 < K; k0 += 16) {
        __syncthreads();
        As[lk + 0][lm]      = a0.x; As[lk + 1][lm]      = a0.y;
        As[lk + 2][lm]      = a0.z; As[lk + 3][lm]      = a0.w;
        As[lk + 0][lm + 64] = a1.x; As[lk + 1][lm + 64] = a1.y;
        As[lk + 2][lm + 64] = a1.z; As[lk + 3][lm + 64] = a1.w;
        Bs[lk + 0][lm]      = b0.x; Bs[lk + 1][lm]      = b0.y;
        Bs[lk + 2][lm]      = b0.z; Bs[lk + 3][lm]      = b0.w;
        Bs[lk + 0][lm + 64] = b1.x; Bs[lk + 1][lm + 64] = b1.y;
        Bs[lk + 2][lm + 64] = b1.z; Bs[lk + 3][lm + 64] = b1.w;
        __syncthreads();

        if (k0 + 16 < K) {  // prefetch next tile while computing this one
            a0 = *(const float4*)(Ag + k0 + 16);
            a1 = *(const float4*)(Ag + 64 * K + k0 + 16);
            b0 = *(const float4*)(Wg + k0 + 16);
            b1 = *(const float4*)(Wg + 64 * K + k0 + 16);
        }

#pragma unroll
        for (int kk = 0; kk < 16; kk++) {
            float4 av0 = *(const float4*)&As[kk][ty * 8];
            float4 av1 = *(const float4*)&As[kk][ty * 8 + 4];
            float4 bv0 = *(const float4*)&Bs[kk][tx * 8];
            float4 bv1 = *(const float4*)&Bs[kk][tx * 8 + 4];
            u64 bp[4] = { pack2(bv0.x, bv0.y), pack2(bv0.z, bv0.w),
                          pack2(bv1.x, bv1.y), pack2(bv1.z, bv1.w) };
            float a[8] = { av0.x, av0.y, av0.z, av0.w, av1.x, av1.y, av1.z, av1.w };
#pragma unroll
            for (int i = 0; i < 8; i++) {
                u64 as = pack2(a[i], a[i]);
#pragma unroll
                for (int j = 0; j < 4; j++) c2[i][j] = fma2(bp[j], as, c2[i][j]);
            }
        }
    }

    float* Cp = g_h + (size_t)(bm + ty * 8) * 1024 + bn + tx * 8;
#pragma unroll
    for (int i = 0; i < 8; i++) {
#pragma unroll
        for (int j = 0; j < 4; j++) {
            float2 v = unpack2(c2[i][j]);
            int col = tx * 8 + 2 * j;
            Cp[(size_t)i * 1024 + 2 * j]     = v.x + bias[bn + col];
            Cp[(size_t)i * 1024 + 2 * j + 1] = v.y + bias[bn + col + 1];
        }
    }
}

// ---------------------------------------------------------------------------
// Kernel 2: RK4 integration of Lorenz96, 100 steps, in-place on g_h.
// Block = 64 threads = one pair of batch rows packed into f32x2 lanes.
// Thread t owns features [16t, 16t+16); halos (i-2,i-1,i+1) via tiny smem.
// ---------------------------------------------------------------------------
__global__ void __launch_bounds__(64) rk4_kernel()
{
    const int t = threadIdx.x;
    float* p0 = g_h + (size_t)(2 * blockIdx.x) * 1024 + t * 16;
    float* p1 = p0 + 1024;

    const u64 NEG1 = pack2(-1.0f, -1.0f);
    const u64 F2   = pack2(8.0f, 8.0f);
    const u64 H05  = pack2(0.005f, 0.005f);
    const u64 H1   = pack2(0.01f, 0.01f);
    const float h6f = 0.01f / 6.0f;
    const u64 H6   = pack2(h6f, h6f);
    const u64 TWO  = pack2(2.0f, 2.0f);

    u64 x[16], y[16], acc[16];
#pragma unroll
    for (int i = 0; i < 16; i++) x[i] = pack2(p0[i], p1[i]);

    __shared__ u64 sA[2][64], sB[2][64], sC[2][64]; // v[14], v[15], v[0] per thread
    const int tl = (t + 63) & 63;
    const int tr = (t + 1) & 63;

    sA[0][t] = x[14]; sB[0][t] = x[15]; sC[0][t] = x[0];
    __syncthreads();
    int pb = 0;

#pragma unroll 1
    for (int s = 0; s < 100; s++) {
        // ---- stage 1: k1 from x; y = x + h/2 k1; acc = k1
        {
            u64 ym2 = sA[pb][tl], ym1 = sB[pb][tl], hp1 = sC[pb][tr];
#pragma unroll
            for (int i = 0; i < 16; i++) {
                u64 vc = x[i];
                u64 vp = (i < 15) ? x[i + 1] : hp1;
                u64 k  = fma2(fma2(ym2, NEG1, vp), ym1, fma2(vc, NEG1, F2));
                acc[i] = k;
                y[i]   = fma2(k, H05, x[i]);
                ym2 = ym1; ym1 = vc;
            }
            pb ^= 1;
            sA[pb][t] = y[14]; sB[pb][t] = y[15]; sC[pb][t] = y[0];
            __syncthreads();
        }
        // ---- stage 2: k2 from y; y = x + h/2 k2; acc += 2 k2
        {
            u64 ym2 = sA[pb][tl], ym1 = sB[pb][tl], hp1 = sC[pb][tr];
#pragma unroll
            for (int i = 0; i < 16; i++) {
                u64 vc = y[i];
                u64 vp = (i < 15) ? y[i + 1] : hp1;
                u64 k  = fma2(fma2(ym2, NEG1, vp), ym1, fma2(vc, NEG1, F2));
                acc[i] = fma2(k, TWO, acc[i]);
                y[i]   = fma2(k, H05, x[i]);
                ym2 = ym1; ym1 = vc;
            }
            pb ^= 1;
            sA[pb][t] = y[14]; sB[pb][t] = y[15]; sC[pb][t] = y[0];
            __syncthreads();
        }
        // ---- stage 3: k3 from y; y = x + h k3; acc += 2 k3
        {
            u64 ym2 = sA[pb][tl], ym1 = sB[pb][tl], hp1 = sC[pb][tr];
#pragma unroll
            for (int i = 0; i < 16; i++) {
                u64 vc = y[i];
                u64 vp = (i < 15) ? y[i + 1] : hp1;
                u64 k  = fma2(fma2(ym2, NEG1, vp), ym1, fma2(vc, NEG1, F2));
                acc[i] = fma2(k, TWO, acc[i]);
                y[i]   = fma2(k, H1, x[i]);
                ym2 = ym1; ym1 = vc;
            }
            pb ^= 1;
            sA[pb][t] = y[14]; sB[pb][t] = y[15]; sC[pb][t] = y[0];
            __syncthreads();
        }
        // ---- stage 4: k4 from y; x += h/6 (acc + k4)
        {
            u64 ym2 = sA[pb][tl], ym1 = sB[pb][tl], hp1 = sC[pb][tr];
#pragma unroll
            for (int i = 0; i < 16; i++) {
                u64 vc = y[i];
                u64 vp = (i < 15) ? y[i + 1] : hp1;
                u64 k  = fma2(fma2(ym2, NEG1, vp), ym1, fma2(vc, NEG1, F2));
                x[i]   = fma2(add2(k, acc[i]), H6, x[i]);
                ym2 = ym1; ym1 = vc;
            }
            pb ^= 1;
            sA[pb][t] = x[14]; sB[pb][t] = x[15]; sC[pb][t] = x[0];
            __syncthreads();
        }
    }

#pragma unroll
    for (int i = 0; i < 16; i++) {
        float2 v = unpack2(x[i]);
        p0[i] = v.x;
        p1[i] = v.y;
    }
}

// ---------------------------------------------------------------------------
// Kernel 3: logits = h @ W2^T + b2, then log_softmax.  One warp per row.
// ---------------------------------------------------------------------------
__global__ void __launch_bounds__(128) head_kernel(
    const float* __restrict__ W2, const float* __restrict__ b2,
    float* __restrict__ out)
{
    __shared__ float w2s[10 * 1024];
    __shared__ float b2s[10];
    const int tid = threadIdx.x;
    for (int i = tid; i < 10 * 1024; i += 128) w2s[i] = W2[i];
    if (tid < 10) b2s[tid] = b2[tid];
    __syncthreads();

    const int warp = tid >> 5;
    const int lane = tid & 31;
    const int row = blockIdx.x * 4 + warp;
    const float* hr = g_h + (size_t)row * 1024;

    float acc[10];
#pragma unroll
    for (int o = 0; o < 10; o++) acc[o] = 0.0f;

#pragma unroll 4
    for (int j = 0; j < 32; j++) {
        float hv = hr[lane + 32 * j];
#pragma unroll
        for (int o = 0; o < 10; o++)
            acc[o] = fmaf(hv, w2s[o * 1024 + lane + 32 * j], acc[o]);
    }
#pragma unroll
    for (int o = 0; o < 10; o++) {
#pragma unroll
        for (int off = 16; off > 0; off >>= 1)
            acc[o] += __shfl_xor_sync(0xFFFFFFFFu, acc[o], off);
    }
    // every lane now holds the full 10 logits
    float lg[10];
    float m = -1e30f;
#pragma unroll
    for (int o = 0; o < 10; o++) { lg[o] = acc[o] + b2s[o]; m = fmaxf(m, lg[o]); }
    float s = 0.0f;
#pragma unroll
    for (int o = 0; o < 10; o++) s += expf(lg[o] - m);
    float lse = logf(s) + m;
    if (lane < 10) out[(size_t)row * 10 + lane] = lg[lane] - lse;
}

// ---------------------------------------------------------------------------
extern "C" void kernel_launch(void* const* d_in, const int* in_sizes, int n_in,
                              void* d_out, int out_size)
{
    const float* x  = (const float*)d_in[0];  // [8192, 784]
    const float* W1 = (const float*)d_in[1];  // [1024, 784]
    const float* b1 = (const float*)d_in[2];  // [1024]
    const float* W2 = (const float*)d_in[3];  // [10, 1024]
    const float* b2 = (const float*)d_in[4];  // [10]
    float* out = (float*)d_out;               // [8192, 10]

    dim3 g1(1024 / 128, 8192 / 128);          // (8, 64)
    sgemm1_kernel<<<g1, 256>>>(x, W1, b1);
    rk4_kernel<<<8192 / 2, 64>>>();
    head_kernel<<<8192 / 4, 128>>>(W2, b2, out);
}

// round 3
// speedup vs baseline: 1.1963x; 1.1963x over previous
#include <cuda_runtime.h>
#include <cstdint>

typedef unsigned long long u64;
typedef unsigned int u32;

// ===================== f32x2 helpers =====================
__device__ __forceinline__ u64 fma2(u64 a, u64 b, u64 c) {
    u64 d; asm("fma.rn.f32x2 %0, %1, %2, %3;" : "=l"(d) : "l"(a), "l"(b), "l"(c)); return d;
}
__device__ __forceinline__ u64 pack2(float lo, float hi) {
    u64 d; asm("mov.b64 %0, {%1, %2};" : "=l"(d) : "f"(lo), "f"(hi)); return d;
}
__device__ __forceinline__ float2 unpack2(u64 v) {
    float2 r; asm("mov.b64 {%0, %1}, %2;" : "=f"(r.x), "=f"(r.y) : "l"(v)); return r;
}

// Scratch hidden state h [8192 x 1024]
__device__ float g_h[8192 * 1024];

// ===================== mma.sync helpers (arch-agnostic PTX) =====================
__device__ __forceinline__ u32 smem_u32(const void* p) {
    u32 a;
    asm("{ .reg .u64 t; cvta.to.shared.u64 t, %1; cvt.u32.u64 %0, t; }" : "=r"(a) : "l"(p));
    return a;
}

#define LDSM4(r, addr) \
    asm volatile("ldmatrix.sync.aligned.m8n8.x4.shared.b16 {%0,%1,%2,%3}, [%4];" \
        : "=r"((r)[0]), "=r"((r)[1]), "=r"((r)[2]), "=r"((r)[3]) : "r"(addr))

#define MMA_BF16(c, a, b) \
    asm volatile("mma.sync.aligned.m16n8k16.row.col.f32.bf16.bf16.f32 " \
        "{%0,%1,%2,%3}, {%4,%5,%6,%7}, {%8,%9}, {%0,%1,%2,%3};" \
        : "+f"((c)[0]), "+f"((c)[1]), "+f"((c)[2]), "+f"((c)[3]) \
        : "r"((a)[0]), "r"((a)[1]), "r"((a)[2]), "r"((a)[3]), \
          "r"((b)[0]), "r"((b)[1]))

// split one float pair into bf16 hi-plane and lo-plane packed words.
// packed low 16 bits = first element (little-endian memory order).
__device__ __forceinline__ void split2(float x, float y, u32& hi, u32& lo) {
    u32 h;
    asm("cvt.rn.bf16x2.f32 %0, %1, %2;" : "=r"(h) : "f"(y), "f"(x)); // hi16=y, lo16=x
    float hx = __uint_as_float(h << 16);
    float hy = __uint_as_float(h & 0xFFFF0000u);
    float lx = x - hx;
    float ly = y - hy;
    u32 l;
    asm("cvt.rn.bf16x2.f32 %0, %1, %2;" : "=r"(l) : "f"(ly), "f"(lx));
    hi = h; lo = l;
}

// ---------------------------------------------------------------------------
// Kernel 1: h = x @ W1^T + b1 via bf16-split mma.sync tensor cores.
// CTA tile 128(M) x 64(N), BK=32 fp32; 8 warps, warp tile 32x32.
// smem planes: Ah/Al [128 rows][40 bf16 stride], Bh/Bl [64][40]. 80B rows:
// 16B-aligned and ldmatrix-conflict-free (banks row*20 mod 32 distinct).
// ---------------------------------------------------------------------------
__global__ void __launch_bounds__(256) gemm1_mma(
    const float* __restrict__ A, const float* __restrict__ W,
    const float* __restrict__ bias)
{
    __shared__ __align__(16) unsigned short sAh[128 * 40];
    __shared__ __align__(16) unsigned short sAl[128 * 40];
    __shared__ __align__(16) unsigned short sBh[64 * 40];
    __shared__ __align__(16) unsigned short sBl[64 * 40];

    const int tid = threadIdx.x;
    const int wid = tid >> 5, lane = tid & 31;
    const int wm = wid >> 1;       // 0..3
    const int wn = wid & 1;        // 0..1
    const int bm = blockIdx.y * 128, bn = blockIdx.x * 64;

    const u32 sb_ah = smem_u32(sAh), sb_al = smem_u32(sAl);
    const u32 sb_bh = smem_u32(sBh), sb_bl = smem_u32(sBl);

    // loader mapping
    const int a_row = tid >> 1;          // 0..127
    const int a_cb  = (tid & 1) * 16;    // 0 or 16
    const int b_row = tid >> 2;          // 0..63
    const int b_cb  = (tid & 3) * 8;     // 0,8,16,24
    const float* Ap = A + (size_t)(bm + a_row) * 784;
    const float* Wp = W + (size_t)(bn + b_row) * 784;

    float4 av[4], bv[2];
    auto LOAD = [&](int kt) {
        const int k0 = kt * 32;
#pragma unroll
        for (int j = 0; j < 4; j++) {
            int c = k0 + a_cb + 4 * j;
            av[j] = (c < 784) ? *(const float4*)(Ap + c) : make_float4(0.f, 0.f, 0.f, 0.f);
        }
#pragma unroll
        for (int j = 0; j < 2; j++) {
            int c = k0 + b_cb + 4 * j;
            bv[j] = (c < 784) ? *(const float4*)(Wp + c) : make_float4(0.f, 0.f, 0.f, 0.f);
        }
    };
    auto STORE = [&]() {
#pragma unroll
        for (int j = 0; j < 4; j++) {
            u32 h01, l01, h23, l23;
            split2(av[j].x, av[j].y, h01, l01);
            split2(av[j].z, av[j].w, h23, l23);
            int off = a_row * 40 + a_cb + 4 * j;  // ushort index, 8B-aligned bytes
            *(uint2*)&sAh[off] = make_uint2(h01, h23);
            *(uint2*)&sAl[off] = make_uint2(l01, l23);
        }
#pragma unroll
        for (int j = 0; j < 2; j++) {
            u32 h01, l01, h23, l23;
            split2(bv[j].x, bv[j].y, h01, l01);
            split2(bv[j].z, bv[j].w, h23, l23);
            int off = b_row * 40 + b_cb + 4 * j;
            *(uint2*)&sBh[off] = make_uint2(h01, h23);
            *(uint2*)&sBl[off] = make_uint2(l01, l23);
        }
    };

    float c[2][4][4];
#pragma unroll
    for (int mf = 0; mf < 2; mf++)
#pragma unroll
        for (int nf = 0; nf < 4; nf++)
#pragma unroll
            for (int r = 0; r < 4; r++) c[mf][nf][r] = 0.0f;

    // ldmatrix per-lane byte offsets (within plane)
    const u32 a_lm = (u32)((wm * 32 + (lane & 15)) * 80 + (lane >> 4) * 16);
    const u32 b_lm = (u32)((wn * 32 + ((lane & 16) >> 1) + (lane & 7)) * 80 + ((lane >> 3) & 1) * 16);

    LOAD(0);

#pragma unroll 1
    for (int kt = 0; kt < 25; kt++) {
        __syncthreads();
        STORE();
        __syncthreads();
        if (kt < 24) LOAD(kt + 1);

#pragma unroll
        for (int ks = 0; ks < 2; ks++) {
            u32 ah[2][4], al[2][4], bh[4][2], bl[4][2];
            const u32 ao = a_lm + ks * 32;
            LDSM4(ah[0], sb_ah + ao);
            LDSM4(ah[1], sb_ah + ao + 16 * 80);
            LDSM4(al[0], sb_al + ao);
            LDSM4(al[1], sb_al + ao + 16 * 80);
            const u32 bo = b_lm + ks * 32;
            {
                u32 t[4];
                LDSM4(t, sb_bh + bo);
                bh[0][0] = t[0]; bh[0][1] = t[1]; bh[1][0] = t[2]; bh[1][1] = t[3];
                LDSM4(t, sb_bh + bo + 16 * 80);
                bh[2][0] = t[0]; bh[2][1] = t[1]; bh[3][0] = t[2]; bh[3][1] = t[3];
                LDSM4(t, sb_bl + bo);
                bl[0][0] = t[0]; bl[0][1] = t[1]; bl[1][0] = t[2]; bl[1][1] = t[3];
                LDSM4(t, sb_bl + bo + 16 * 80);
                bl[2][0] = t[0]; bl[2][1] = t[1]; bl[3][0] = t[2]; bl[3][1] = t[3];
            }
#pragma unroll
            for (int mf = 0; mf < 2; mf++)
#pragma unroll
                for (int nf = 0; nf < 4; nf++) {
                    MMA_BF16(c[mf][nf], ah[mf], bh[nf]);
                    MMA_BF16(c[mf][nf], ah[mf], bl[nf]);
                    MMA_BF16(c[mf][nf], al[mf], bh[nf]);
                }
        }
    }

    // epilogue: C + bias -> g_h
#pragma unroll
    for (int mf = 0; mf < 2; mf++) {
#pragma unroll
        for (int nf = 0; nf < 4; nf++) {
            const int row = bm + wm * 32 + mf * 16 + (lane >> 2);
            const int col = bn + wn * 32 + nf * 8 + (lane & 3) * 2;
            const float b0 = bias[col], b1 = bias[col + 1];
            float2 v0 = make_float2(c[mf][nf][0] + b0, c[mf][nf][1] + b1);
            float2 v1 = make_float2(c[mf][nf][2] + b0, c[mf][nf][3] + b1);
            *(float2*)(g_h + (size_t)row * 1024 + col) = v0;
            *(float2*)(g_h + (size_t)(row + 8) * 1024 + col) = v1;
        }
    }
}

// ---------------------------------------------------------------------------
// Kernel 2: RK4 Lorenz96, 100 steps, f32x2 over batch pairs.
// xacc scheme: xacc accumulates x + h/6 k1 + h/3 k2 + h/3 k3 (+ h/6 k4).
// ---------------------------------------------------------------------------
__global__ void __launch_bounds__(64) rk4_kernel()
{
    const int t = threadIdx.x;
    float* p0 = g_h + (size_t)(2 * blockIdx.x) * 1024 + t * 16;
    float* p1 = p0 + 1024;

    const u64 NEG1 = pack2(-1.0f, -1.0f);
    const u64 F2   = pack2(8.0f, 8.0f);
    const u64 H05  = pack2(0.005f, 0.005f);
    const u64 H1   = pack2(0.01f, 0.01f);
    const float h6f = 0.01f / 6.0f;
    const float h3f = 0.01f / 3.0f;
    const u64 H6 = pack2(h6f, h6f);
    const u64 H3 = pack2(h3f, h3f);

    u64 x[16], y[16], xa[16];
#pragma unroll
    for (int i = 0; i < 16; i++) x[i] = pack2(p0[i], p1[i]);

    __shared__ u64 sA[2][64], sB[2][64], sC[2][64];
    const int tl = (t + 63) & 63;
    const int tr = (t + 1) & 63;

    sA[0][t] = x[14]; sB[0][t] = x[15]; sC[0][t] = x[0];
    __syncthreads();
    int pb = 0;

#pragma unroll 1
    for (int s = 0; s < 100; s++) {
        {   // stage 1: k1 from x
            u64 ym2 = sA[pb][tl], ym1 = sB[pb][tl], hp1 = sC[pb][tr];
#pragma unroll
            for (int i = 0; i < 16; i++) {
                u64 vc = x[i];
                u64 vp = (i < 15) ? x[i + 1] : hp1;
                u64 k  = fma2(fma2(ym2, NEG1, vp), ym1, fma2(vc, NEG1, F2));
                xa[i]  = fma2(k, H6, x[i]);
                y[i]   = fma2(k, H05, x[i]);
                ym2 = ym1; ym1 = vc;
            }
            pb ^= 1;
            sA[pb][t] = y[14]; sB[pb][t] = y[15]; sC[pb][t] = y[0];
            __syncthreads();
        }
        {   // stage 2: k2 from y
            u64 ym2 = sA[pb][tl], ym1 = sB[pb][tl], hp1 = sC[pb][tr];
#pragma unroll
            for (int i = 0; i < 16; i++) {
                u64 vc = y[i];
                u64 vp = (i < 15) ? y[i + 1] : hp1;
                u64 k  = fma2(fma2(ym2, NEG1, vp), ym1, fma2(vc, NEG1, F2));
                xa[i]  = fma2(k, H3, xa[i]);
                y[i]   = fma2(k, H05, x[i]);
                ym2 = ym1; ym1 = vc;
            }
            pb ^= 1;
            sA[pb][t] = y[14]; sB[pb][t] = y[15]; sC[pb][t] = y[0];
            __syncthreads();
        }
        {   // stage 3: k3 from y
            u64 ym2 = sA[pb][tl], ym1 = sB[pb][tl], hp1 = sC[pb][tr];
#pragma unroll
            for (int i = 0; i < 16; i++) {
                u64 vc = y[i];
                u64 vp = (i < 15) ? y[i + 1] : hp1;
                u64 k  = fma2(fma2(ym2, NEG1, vp), ym1, fma2(vc, NEG1, F2));
                xa[i]  = fma2(k, H3, xa[i]);
                y[i]   = fma2(k, H1, x[i]);
                ym2 = ym1; ym1 = vc;
            }
            pb ^= 1;
            sA[pb][t] = y[14]; sB[pb][t] = y[15]; sC[pb][t] = y[0];
            __syncthreads();
        }
        {   // stage 4: k4 from y; x = xacc + h/6 k4
            u64 ym2 = sA[pb][tl], ym1 = sB[pb][tl], hp1 = sC[pb][tr];
#pragma unroll
            for (int i = 0; i < 16; i++) {
                u64 vc = y[i];
                u64 vp = (i < 15) ? y[i + 1] : hp1;
                u64 k  = fma2(fma2(ym2, NEG1, vp), ym1, fma2(vc, NEG1, F2));
                x[i]   = fma2(k, H6, xa[i]);
                ym2 = ym1; ym1 = vc;
            }
            pb ^= 1;
            sA[pb][t] = x[14]; sB[pb][t] = x[15]; sC[pb][t] = x[0];
            __syncthreads();
        }
    }

#pragma unroll
    for (int i = 0; i < 16; i++) {
        float2 v = unpack2(x[i]);
        p0[i] = v.x;
        p1[i] = v.y;
    }
}

// ---------------------------------------------------------------------------
// Kernel 3: logits = h @ W2^T + b2, log_softmax.
// ---------------------------------------------------------------------------
__global__ void __launch_bounds__(128) head_kernel(
    const float* __restrict__ W2, const float* __restrict__ b2,
    float* __restrict__ out)
{
    __shared__ float w2s[10 * 1024];
    __shared__ float b2s[10];
    const int tid = threadIdx.x;
    for (int i = tid; i < 10 * 1024; i += 128) w2s[i] = W2[i];
    if (tid < 10) b2s[tid] = b2[tid];
    __syncthreads();

    const int warp = tid >> 5;
    const int lane = tid & 31;
    const int row = blockIdx.x * 4 + warp;
    const float* hr = g_h + (size_t)row * 1024;

    float acc[10];
#pragma unroll
    for (int o = 0; o < 10; o++) acc[o] = 0.0f;

#pragma unroll 4
    for (int j = 0; j < 32; j++) {
        float hv = hr[lane + 32 * j];
#pragma unroll
        for (int o = 0; o < 10; o++)
            acc[o] = fmaf(hv, w2s[o * 1024 + lane + 32 * j], acc[o]);
    }
#pragma unroll
    for (int o = 0; o < 10; o++) {
#pragma unroll
        for (int off = 16; off > 0; off >>= 1)
            acc[o] += __shfl_xor_sync(0xFFFFFFFFu, acc[o], off);
    }
    float lg[10];
    float m = -1e30f;
#pragma unroll
    for (int o = 0; o < 10; o++) { lg[o] = acc[o] + b2s[o]; m = fmaxf(m, lg[o]); }
    float s = 0.0f;
#pragma unroll
    for (int o = 0; o < 10; o++) s += expf(lg[o] - m);
    float lse = logf(s) + m;
    if (lane < 10) out[(size_t)row * 10 + lane] = lg[lane] - lse;
}

// ---------------------------------------------------------------------------
extern "C" void kernel_launch(void* const* d_in, const int* in_sizes, int n_in,
                              void* d_out, int out_size)
{
    const float* x  = (const float*)d_in[0];  // [8192, 784]
    const float* W1 = (const float*)d_in[1];  // [1024, 784]
    const float* b1 = (const float*)d_in[2];  // [1024]
    const float* W2 = (const float*)d_in[3];  // [10, 1024]
    const float* b2 = (const float*)d_in[4];  // [10]
    float* out = (float*)d_out;               // [8192, 10]

    dim3 g1(1024 / 64, 8192 / 128);           // (16, 64)
    gemm1_mma<<<g1, 256>>>(x, W1, b1);
    rk4_kernel<<<8192 / 2, 64>>>();
    head_kernel<<<8192 / 4, 128>>>(W2, b2, out);
}

// round 4
// speedup vs baseline: 1.6052x; 1.3418x over previous
#include <cuda_runtime.h>
#include <cstdint>

typedef unsigned long long u64;
typedef unsigned int u32;

// ===================== f32x2 helpers =====================
__device__ __forceinline__ u64 fma2(u64 a, u64 b, u64 c) {
    u64 d; asm("fma.rn.f32x2 %0, %1, %2, %3;" : "=l"(d) : "l"(a), "l"(b), "l"(c)); return d;
}
__device__ __forceinline__ u64 pack2(float lo, float hi) {
    u64 d; asm("mov.b64 %0, {%1, %2};" : "=l"(d) : "f"(lo), "f"(hi)); return d;
}
__device__ __forceinline__ float2 unpack2(u64 v) {
    float2 r; asm("mov.b64 {%0, %1}, %2;" : "=f"(r.x), "=f"(r.y) : "l"(v)); return r;
}

// Scratch hidden state h [8192 x 1024]
__device__ float g_h[8192 * 1024];

// ===================== mma.sync helpers =====================
__device__ __forceinline__ u32 smem_u32(const void* p) {
    u32 a;
    asm("{ .reg .u64 t; cvta.to.shared.u64 t, %1; cvt.u32.u64 %0, t; }" : "=r"(a) : "l"(p));
    return a;
}

#define LDSM4(r, addr) \
    asm volatile("ldmatrix.sync.aligned.m8n8.x4.shared.b16 {%0,%1,%2,%3}, [%4];" \
        : "=r"((r)[0]), "=r"((r)[1]), "=r"((r)[2]), "=r"((r)[3]) : "r"(addr))

#define MMA_BF16(c, a, b) \
    asm volatile("mma.sync.aligned.m16n8k16.row.col.f32.bf16.bf16.f32 " \
        "{%0,%1,%2,%3}, {%4,%5,%6,%7}, {%8,%9}, {%0,%1,%2,%3};" \
        : "+f"((c)[0]), "+f"((c)[1]), "+f"((c)[2]), "+f"((c)[3]) \
        : "r"((a)[0]), "r"((a)[1]), "r"((a)[2]), "r"((a)[3]), \
          "r"((b)[0]), "r"((b)[1]))

// split float pair -> bf16 hi-plane word + lo-plane word (lo16 = first elem)
__device__ __forceinline__ void split2(float x, float y, u32& hi, u32& lo) {
    u32 h;
    asm("cvt.rn.bf16x2.f32 %0, %1, %2;" : "=r"(h) : "f"(y), "f"(x));
    float hx = __uint_as_float(h << 16);
    float hy = __uint_as_float(h & 0xFFFF0000u);
    float lx = x - hx;
    float ly = y - hy;
    u32 l;
    asm("cvt.rn.bf16x2.f32 %0, %1, %2;" : "=r"(l) : "f"(ly), "f"(lx));
    hi = h; lo = l;
}

// smem plane geometry: 128 rows x 40 ushort (80B stride), per-buffer 4 planes
static constexpr int PLANE_B  = 128 * 40 * 2;     // 10240 bytes per plane
static constexpr int STAGE_B  = 4 * PLANE_B;      // 40960 per buffer
static constexpr int GEMM_SMEM = 2 * STAGE_B;     // 81920 dynamic

// ---------------------------------------------------------------------------
// Kernel 1: h = x @ W1^T + b1, bf16-split (3 products) mma.sync.
// CTA 128(M) x 128(N), BK=32 fp32, 8 warps, warp tile 64x32, double-buffered.
// ---------------------------------------------------------------------------
__global__ void __launch_bounds__(256) gemm1_mma(
    const float* __restrict__ A, const float* __restrict__ W,
    const float* __restrict__ bias)
{
    extern __shared__ __align__(16) char dsm[];
    const u32 sb = smem_u32(dsm);

    const int tid = threadIdx.x;
    const int wid = tid >> 5, lane = tid & 31;
    const int wm = wid >> 2;       // 0..1  (64-row band)
    const int wn = wid & 3;        // 0..3  (32-col band)
    const int bm = blockIdx.y * 128, bn = blockIdx.x * 128;

    // loader: thread -> (row 0..127, 16-col half); both A and B are 128x32 fp32
    const int a_row = tid >> 1;
    const int a_cb  = (tid & 1) * 16;
    const float* Ap = A + (size_t)(bm + a_row) * 784;
    const float* Wp = W + (size_t)(bn + a_row) * 784;

    float4 av[4], bv[4];
    auto LOAD = [&](int kt) {
        const int k0 = kt * 32 + a_cb;
#pragma unroll
        for (int j = 0; j < 4; j++) {
            int c = k0 + 4 * j;
            if (c < 784) { av[j] = *(const float4*)(Ap + c); bv[j] = *(const float4*)(Wp + c); }
            else { av[j] = make_float4(0.f, 0.f, 0.f, 0.f); bv[j] = av[j]; }
        }
    };
    auto STORE = [&](int s) {
        char* base = dsm + s * STAGE_B;
        unsigned short* pAh = (unsigned short*)(base);
        unsigned short* pAl = (unsigned short*)(base + PLANE_B);
        unsigned short* pBh = (unsigned short*)(base + 2 * PLANE_B);
        unsigned short* pBl = (unsigned short*)(base + 3 * PLANE_B);
        const int off0 = a_row * 40 + a_cb;
#pragma unroll
        for (int j = 0; j < 4; j++) {
            u32 h01, l01, h23, l23;
            split2(av[j].x, av[j].y, h01, l01);
            split2(av[j].z, av[j].w, h23, l23);
            *(uint2*)&pAh[off0 + 4 * j] = make_uint2(h01, h23);
            *(uint2*)&pAl[off0 + 4 * j] = make_uint2(l01, l23);
            split2(bv[j].x, bv[j].y, h01, l01);
            split2(bv[j].z, bv[j].w, h23, l23);
            *(uint2*)&pBh[off0 + 4 * j] = make_uint2(h01, h23);
            *(uint2*)&pBl[off0 + 4 * j] = make_uint2(l01, l23);
        }
    };

    float c[4][4][4];
#pragma unroll
    for (int mf = 0; mf < 4; mf++)
#pragma unroll
        for (int nf = 0; nf < 4; nf++)
#pragma unroll
            for (int r = 0; r < 4; r++) c[mf][nf][r] = 0.0f;

    // ldmatrix per-lane byte offsets within a plane
    const u32 a_lm = (u32)((wm * 64 + (lane & 15)) * 80 + (lane >> 4) * 16);
    const u32 b_lm = (u32)((wn * 32 + ((lane & 16) >> 1) + (lane & 7)) * 80 + ((lane >> 3) & 1) * 16);

    LOAD(0);
    int s = 0;

#pragma unroll 1
    for (int kt = 0; kt < 25; kt++) {
        STORE(s);
        __syncthreads();
        if (kt < 24) LOAD(kt + 1);

        const u32 bufb = sb + s * STAGE_B;
#pragma unroll
        for (int ks = 0; ks < 2; ks++) {
            u32 ah[4][4], al[4][4], bh[4][2], bl[4][2];
            const u32 ao = bufb + a_lm + ks * 32;
#pragma unroll
            for (int mf = 0; mf < 4; mf++) {
                LDSM4(ah[mf], ao + mf * 16 * 80);
                LDSM4(al[mf], ao + PLANE_B + mf * 16 * 80);
            }
            const u32 bo = bufb + 2 * PLANE_B + b_lm + ks * 32;
            {
                u32 t[4];
                LDSM4(t, bo);
                bh[0][0] = t[0]; bh[0][1] = t[1]; bh[1][0] = t[2]; bh[1][1] = t[3];
                LDSM4(t, bo + 16 * 80);
                bh[2][0] = t[0]; bh[2][1] = t[1]; bh[3][0] = t[2]; bh[3][1] = t[3];
                LDSM4(t, bo + PLANE_B);
                bl[0][0] = t[0]; bl[0][1] = t[1]; bl[1][0] = t[2]; bl[1][1] = t[3];
                LDSM4(t, bo + PLANE_B + 16 * 80);
                bl[2][0] = t[0]; bl[2][1] = t[1]; bl[3][0] = t[2]; bl[3][1] = t[3];
            }
#pragma unroll
            for (int mf = 0; mf < 4; mf++)
#pragma unroll
                for (int nf = 0; nf < 4; nf++) {
                    MMA_BF16(c[mf][nf], ah[mf], bh[nf]);
                    MMA_BF16(c[mf][nf], ah[mf], bl[nf]);
                    MMA_BF16(c[mf][nf], al[mf], bh[nf]);
                }
        }
        s ^= 1;
    }

    // epilogue: C + bias -> g_h
#pragma unroll
    for (int mf = 0; mf < 4; mf++) {
#pragma unroll
        for (int nf = 0; nf < 4; nf++) {
            const int row = bm + wm * 64 + mf * 16 + (lane >> 2);
            const int col = bn + wn * 32 + nf * 8 + (lane & 3) * 2;
            const float b0 = bias[col], b1 = bias[col + 1];
            float2 v0 = make_float2(c[mf][nf][0] + b0, c[mf][nf][1] + b1);
            float2 v1 = make_float2(c[mf][nf][2] + b0, c[mf][nf][3] + b1);
            *(float2*)(g_h + (size_t)row * 1024 + col) = v0;
            *(float2*)(g_h + (size_t)(row + 8) * 1024 + col) = v1;
        }
    }
}

// ---------------------------------------------------------------------------
// Kernel 2: RK4 Lorenz96 over [0,1] with h=1/64 (64 steps).
// f32x2 over batch pairs; progressive accumulator (19 ops/elem/stage-set).
// ---------------------------------------------------------------------------
__global__ void __launch_bounds__(64) rk4_kernel()
{
    const int t = threadIdx.x;
    float* p0 = g_h + (size_t)(2 * blockIdx.x) * 1024 + t * 16;
    float* p1 = p0 + 1024;

    const float hf = 1.0f / 64.0f;
    const u64 NEG1 = pack2(-1.0f, -1.0f);
    const u64 F2   = pack2(8.0f, 8.0f);
    const u64 H05  = pack2(hf * 0.5f, hf * 0.5f);
    const u64 H1   = pack2(hf, hf);
    const u64 H6   = pack2(hf / 6.0f, hf / 6.0f);
    const u64 H3   = pack2(hf / 3.0f, hf / 3.0f);

    u64 x[16], y[16], xa[16];
#pragma unroll
    for (int i = 0; i < 16; i++) x[i] = pack2(p0[i], p1[i]);

    __shared__ u64 sA[2][64], sB[2][64], sC[2][64];
    const int tl = (t + 63) & 63;
    const int tr = (t + 1) & 63;

    sA[0][t] = x[14]; sB[0][t] = x[15]; sC[0][t] = x[0];
    __syncthreads();
    int pb = 0;

#pragma unroll 1
    for (int s = 0; s < 64; s++) {
        {   // stage 1: k1 from x
            u64 ym2 = sA[pb][tl], ym1 = sB[pb][tl], hp1 = sC[pb][tr];
#pragma unroll
            for (int i = 0; i < 16; i++) {
                u64 vc = x[i];
                u64 vp = (i < 15) ? x[i + 1] : hp1;
                u64 k  = fma2(fma2(ym2, NEG1, vp), ym1, fma2(vc, NEG1, F2));
                xa[i]  = fma2(k, H6, x[i]);
                y[i]   = fma2(k, H05, x[i]);
                ym2 = ym1; ym1 = vc;
            }
            pb ^= 1;
            sA[pb][t] = y[14]; sB[pb][t] = y[15]; sC[pb][t] = y[0];
            __syncthreads();
        }
        {   // stage 2: k2 from y
            u64 ym2 = sA[pb][tl], ym1 = sB[pb][tl], hp1 = sC[pb][tr];
#pragma unroll
            for (int i = 0; i < 16; i++) {
                u64 vc = y[i];
                u64 vp = (i < 15) ? y[i + 1] : hp1;
                u64 k  = fma2(fma2(ym2, NEG1, vp), ym1, fma2(vc, NEG1, F2));
                xa[i]  = fma2(k, H3, xa[i]);
                y[i]   = fma2(k, H05, x[i]);
                ym2 = ym1; ym1 = vc;
            }
            pb ^= 1;
            sA[pb][t] = y[14]; sB[pb][t] = y[15]; sC[pb][t] = y[0];
            __syncthreads();
        }
        {   // stage 3: k3 from y
            u64 ym2 = sA[pb][tl], ym1 = sB[pb][tl], hp1 = sC[pb][tr];
#pragma unroll
            for (int i = 0; i < 16; i++) {
                u64 vc = y[i];
                u64 vp = (i < 15) ? y[i + 1] : hp1;
                u64 k  = fma2(fma2(ym2, NEG1, vp), ym1, fma2(vc, NEG1, F2));
                xa[i]  = fma2(k, H3, xa[i]);
                y[i]   = fma2(k, H1, x[i]);
                ym2 = ym1; ym1 = vc;
            }
            pb ^= 1;
            sA[pb][t] = y[14]; sB[pb][t] = y[15]; sC[pb][t] = y[0];
            __syncthreads();
        }
        {   // stage 4: k4 from y; x = xa + h/6 k4
            u64 ym2 = sA[pb][tl], ym1 = sB[pb][tl], hp1 = sC[pb][tr];
#pragma unroll
            for (int i = 0; i < 16; i++) {
                u64 vc = y[i];
                u64 vp = (i < 15) ? y[i + 1] : hp1;
                u64 k  = fma2(fma2(ym2, NEG1, vp), ym1, fma2(vc, NEG1, F2));
                x[i]   = fma2(k, H6, xa[i]);
                ym2 = ym1; ym1 = vc;
            }
            pb ^= 1;
            sA[pb][t] = x[14]; sB[pb][t] = x[15]; sC[pb][t] = x[0];
            __syncthreads();
        }
    }

#pragma unroll
    for (int i = 0; i < 16; i++) {
        float2 v = unpack2(x[i]);
        p0[i] = v.x;
        p1[i] = v.y;
    }
}

// ---------------------------------------------------------------------------
// Kernel 3: logits = h @ W2^T + b2, log_softmax.
// ---------------------------------------------------------------------------
__global__ void __launch_bounds__(128) head_kernel(
    const float* __restrict__ W2, const float* __restrict__ b2,
    float* __restrict__ out)
{
    __shared__ float w2s[10 * 1024];
    __shared__ float b2s[10];
    const int tid = threadIdx.x;
    for (int i = tid; i < 10 * 1024; i += 128) w2s[i] = W2[i];
    if (tid < 10) b2s[tid] = b2[tid];
    __syncthreads();

    const int warp = tid >> 5;
    const int lane = tid & 31;
    const int row = blockIdx.x * 4 + warp;
    const float* hr = g_h + (size_t)row * 1024;

    float acc[10];
#pragma unroll
    for (int o = 0; o < 10; o++) acc[o] = 0.0f;

#pragma unroll 4
    for (int j = 0; j < 32; j++) {
        float hv = hr[lane + 32 * j];
#pragma unroll
        for (int o = 0; o < 10; o++)
            acc[o] = fmaf(hv, w2s[o * 1024 + lane + 32 * j], acc[o]);
    }
#pragma unroll
    for (int o = 0; o < 10; o++) {
#pragma unroll
        for (int off = 16; off > 0; off >>= 1)
            acc[o] += __shfl_xor_sync(0xFFFFFFFFu, acc[o], off);
    }
    float lg[10];
    float m = -1e30f;
#pragma unroll
    for (int o = 0; o < 10; o++) { lg[o] = acc[o] + b2s[o]; m = fmaxf(m, lg[o]); }
    float s = 0.0f;
#pragma unroll
    for (int o = 0; o < 10; o++) s += expf(lg[o] - m);
    float lse = logf(s) + m;
    if (lane < 10) out[(size_t)row * 10 + lane] = lg[lane] - lse;
}

// ---------------------------------------------------------------------------
extern "C" void kernel_launch(void* const* d_in, const int* in_sizes, int n_in,
                              void* d_out, int out_size)
{
    const float* x  = (const float*)d_in[0];  // [8192, 784]
    const float* W1 = (const float*)d_in[1];  // [1024, 784]
    const float* b1 = (const float*)d_in[2];  // [1024]
    const float* W2 = (const float*)d_in[3];  // [10, 1024]
    const float* b2 = (const float*)d_in[4];  // [10]
    float* out = (float*)d_out;               // [8192, 10]

    cudaFuncSetAttribute(gemm1_mma, cudaFuncAttributeMaxDynamicSharedMemorySize, GEMM_SMEM);

    dim3 g1(1024 / 128, 8192 / 128);          // (8, 64)
    gemm1_mma<<<g1, 256, GEMM_SMEM>>>(x, W1, b1);
    rk4_kernel<<<8192 / 2, 64>>>();
    head_kernel<<<8192 / 4, 128>>>(W2, b2, out);
}

// round 5
// speedup vs baseline: 2.3527x; 1.4657x over previous
#include <cuda_runtime.h>
#include <cstdint>

typedef unsigned long long u64;
typedef unsigned int u32;

// ===================== f32x2 helpers =====================
__device__ __forceinline__ u64 fma2(u64 a, u64 b, u64 c) {
    u64 d; asm("fma.rn.f32x2 %0, %1, %2, %3;" : "=l"(d) : "l"(a), "l"(b), "l"(c)); return d;
}
__device__ __forceinline__ u64 pack2(float lo, float hi) {
    u64 d; asm("mov.b64 %0, {%1, %2};" : "=l"(d) : "f"(lo), "f"(hi)); return d;
}
__device__ __forceinline__ float2 unpack2(u64 v) {
    float2 r; asm("mov.b64 {%0, %1}, %2;" : "=f"(r.x), "=f"(r.y) : "l"(v)); return r;
}

// Scratch hidden state h [8192 x 1024]
__device__ float g_h[8192 * 1024];

// ===================== mma.sync helpers =====================
__device__ __forceinline__ u32 smem_u32(const void* p) {
    u32 a;
    asm("{ .reg .u64 t; cvta.to.shared.u64 t, %1; cvt.u32.u64 %0, t; }" : "=r"(a) : "l"(p));
    return a;
}

#define LDSM4(r, addr) \
    asm volatile("ldmatrix.sync.aligned.m8n8.x4.shared.b16 {%0,%1,%2,%3}, [%4];" \
        : "=r"((r)[0]), "=r"((r)[1]), "=r"((r)[2]), "=r"((r)[3]) : "r"(addr))

#define MMA_BF16(c, a, b) \
    asm volatile("mma.sync.aligned.m16n8k16.row.col.f32.bf16.bf16.f32 " \
        "{%0,%1,%2,%3}, {%4,%5,%6,%7}, {%8,%9}, {%0,%1,%2,%3};" \
        : "+f"((c)[0]), "+f"((c)[1]), "+f"((c)[2]), "+f"((c)[3]) \
        : "r"((a)[0]), "r"((a)[1]), "r"((a)[2]), "r"((a)[3]), \
          "r"((b)[0]), "r"((b)[1]))

// split float pair -> bf16 hi-plane word + lo-plane word (lo16 = first elem)
__device__ __forceinline__ void split2(float x, float y, u32& hi, u32& lo) {
    u32 h;
    asm("cvt.rn.bf16x2.f32 %0, %1, %2;" : "=r"(h) : "f"(y), "f"(x));
    float hx = __uint_as_float(h << 16);
    float hy = __uint_as_float(h & 0xFFFF0000u);
    float lx = x - hx;
    float ly = y - hy;
    u32 l;
    asm("cvt.rn.bf16x2.f32 %0, %1, %2;" : "=r"(l) : "f"(ly), "f"(lx));
    hi = h; lo = l;
}

// smem plane geometry: 128 rows x 40 ushort (80B stride), per-buffer 4 planes
static constexpr int PLANE_B  = 128 * 40 * 2;     // 10240 bytes per plane
static constexpr int STAGE_B  = 4 * PLANE_B;      // 40960 per buffer
static constexpr int GEMM_SMEM = 2 * STAGE_B;     // 81920 dynamic

struct Frags {
    u32 ah[4][4];
    u32 al[4][4];
    u32 bh[4][2];
    u32 bl[4][2];
};

// ---------------------------------------------------------------------------
// Kernel 1: h = x @ W1^T + b1, bf16-split (3 products) mma.sync.
// CTA 128x128, BK=32 fp32, 8 warps, warp tile 64x32, smem double-buffered,
// fragment-level software pipeline (LDSM for next slice under current MMAs).
// ---------------------------------------------------------------------------
__global__ void __launch_bounds__(256) gemm1_mma(
    const float* __restrict__ A, const float* __restrict__ W,
    const float* __restrict__ bias)
{
    extern __shared__ __align__(16) char dsm[];
    const u32 sb = smem_u32(dsm);

    const int tid = threadIdx.x;
    const int wid = tid >> 5, lane = tid & 31;
    const int wm = wid >> 2;       // 0..1  (64-row band)
    const int wn = wid & 3;        // 0..3  (32-col band)
    const int bm = blockIdx.y * 128, bn = blockIdx.x * 128;

    // loader: thread -> (row 0..127, 16-col half)
    const int a_row = tid >> 1;
    const int a_cb  = (tid & 1) * 16;
    const float* Ap = A + (size_t)(bm + a_row) * 784;
    const float* Wp = W + (size_t)(bn + a_row) * 784;

    float4 av[4], bv[4];
    auto LOAD = [&](int kt) {
        const int k0 = kt * 32 + a_cb;
#pragma unroll
        for (int j = 0; j < 4; j++) {
            int c = k0 + 4 * j;
            if (c < 784) { av[j] = *(const float4*)(Ap + c); bv[j] = *(const float4*)(Wp + c); }
            else { av[j] = make_float4(0.f, 0.f, 0.f, 0.f); bv[j] = av[j]; }
        }
    };
    auto STORE = [&](int s) {
        char* base = dsm + s * STAGE_B;
        unsigned short* pAh = (unsigned short*)(base);
        unsigned short* pAl = (unsigned short*)(base + PLANE_B);
        unsigned short* pBh = (unsigned short*)(base + 2 * PLANE_B);
        unsigned short* pBl = (unsigned short*)(base + 3 * PLANE_B);
        const int off0 = a_row * 40 + a_cb;
#pragma unroll
        for (int j = 0; j < 4; j++) {
            u32 h01, l01, h23, l23;
            split2(av[j].x, av[j].y, h01, l01);
            split2(av[j].z, av[j].w, h23, l23);
            *(uint2*)&pAh[off0 + 4 * j] = make_uint2(h01, h23);
            *(uint2*)&pAl[off0 + 4 * j] = make_uint2(l01, l23);
            split2(bv[j].x, bv[j].y, h01, l01);
            split2(bv[j].z, bv[j].w, h23, l23);
            *(uint2*)&pBh[off0 + 4 * j] = make_uint2(h01, h23);
            *(uint2*)&pBl[off0 + 4 * j] = make_uint2(l01, l23);
        }
    };

    float c[4][4][4];
#pragma unroll
    for (int mf = 0; mf < 4; mf++)
#pragma unroll
        for (int nf = 0; nf < 4; nf++)
#pragma unroll
            for (int r = 0; r < 4; r++) c[mf][nf][r] = 0.0f;

    // ldmatrix per-lane byte offsets within a plane
    const u32 a_lm = (u32)((wm * 64 + (lane & 15)) * 80 + (lane >> 4) * 16);
    const u32 b_lm = (u32)((wn * 32 + ((lane & 16) >> 1) + (lane & 7)) * 80 + ((lane >> 3) & 1) * 16);

    Frags f[2];
    auto LDFRAGS = [&](Frags& fr, int s, int ks) {
        const u32 bufb = sb + s * STAGE_B;
        const u32 ao = bufb + a_lm + ks * 32;
#pragma unroll
        for (int mf = 0; mf < 4; mf++) {
            LDSM4(fr.ah[mf], ao + mf * 16 * 80);
            LDSM4(fr.al[mf], ao + PLANE_B + mf * 16 * 80);
        }
        const u32 bo = bufb + 2 * PLANE_B + b_lm + ks * 32;
        u32 t[4];
        LDSM4(t, bo);
        fr.bh[0][0] = t[0]; fr.bh[0][1] = t[1]; fr.bh[1][0] = t[2]; fr.bh[1][1] = t[3];
        LDSM4(t, bo + 16 * 80);
        fr.bh[2][0] = t[0]; fr.bh[2][1] = t[1]; fr.bh[3][0] = t[2]; fr.bh[3][1] = t[3];
        LDSM4(t, bo + PLANE_B);
        fr.bl[0][0] = t[0]; fr.bl[0][1] = t[1]; fr.bl[1][0] = t[2]; fr.bl[1][1] = t[3];
        LDSM4(t, bo + PLANE_B + 16 * 80);
        fr.bl[2][0] = t[0]; fr.bl[2][1] = t[1]; fr.bl[3][0] = t[2]; fr.bl[3][1] = t[3];
    };
    auto MMAS = [&](Frags& fr) {
#pragma unroll
        for (int mf = 0; mf < 4; mf++)
#pragma unroll
            for (int nf = 0; nf < 4; nf++) {
                MMA_BF16(c[mf][nf], fr.ah[mf], fr.bh[nf]);
                MMA_BF16(c[mf][nf], fr.ah[mf], fr.bl[nf]);
                MMA_BF16(c[mf][nf], fr.al[mf], fr.bh[nf]);
            }
    };

    // prologue: tile 0 in buffer 0, tile 1 staged in regs, frags(buf0, ks0) loaded
    LOAD(0);
    STORE(0);
    LOAD(1);
    __syncthreads();
    LDFRAGS(f[0], 0, 0);

#pragma unroll 1
    for (int kt = 0; kt < 25; kt++) {
        const int s = kt & 1;
        LDFRAGS(f[1], s, 1);        // slice ks1, latency hidden under ks0 MMAs
        MMAS(f[0]);
        if (kt < 24) {
            STORE(s ^ 1);           // tile kt+1 (in av/bv) -> other buffer
            if (kt < 23) LOAD(kt + 2);
        }
        MMAS(f[1]);
        __syncthreads();
        if (kt < 24) LDFRAGS(f[0], s ^ 1, 0);   // next tile, slice ks0
    }

    // epilogue: C + bias -> g_h
#pragma unroll
    for (int mf = 0; mf < 4; mf++) {
#pragma unroll
        for (int nf = 0; nf < 4; nf++) {
            const int row = bm + wm * 64 + mf * 16 + (lane >> 2);
            const int col = bn + wn * 32 + nf * 8 + (lane & 3) * 2;
            const float b0 = bias[col], b1 = bias[col + 1];
            float2 v0 = make_float2(c[mf][nf][0] + b0, c[mf][nf][1] + b1);
            float2 v1 = make_float2(c[mf][nf][2] + b0, c[mf][nf][3] + b1);
            *(float2*)(g_h + (size_t)row * 1024 + col) = v0;
            *(float2*)(g_h + (size_t)(row + 8) * 1024 + col) = v1;
        }
    }
}

// ---------------------------------------------------------------------------
// Kernel 2: RK4 Lorenz96 over [0,1] with h=1/32 (32 steps).
// f32x2 over batch pairs; progressive accumulator.
// ---------------------------------------------------------------------------
__global__ void __launch_bounds__(64) rk4_kernel()
{
    const int t = threadIdx.x;
    float* p0 = g_h + (size_t)(2 * blockIdx.x) * 1024 + t * 16;
    float* p1 = p0 + 1024;

    const float hf = 1.0f / 32.0f;
    const u64 NEG1 = pack2(-1.0f, -1.0f);
    const u64 F2   = pack2(8.0f, 8.0f);
    const u64 H05  = pack2(hf * 0.5f, hf * 0.5f);
    const u64 H1   = pack2(hf, hf);
    const u64 H6   = pack2(hf / 6.0f, hf / 6.0f);
    const u64 H3   = pack2(hf / 3.0f, hf / 3.0f);

    u64 x[16], y[16], xa[16];
#pragma unroll
    for (int i = 0; i < 16; i++) x[i] = pack2(p0[i], p1[i]);

    __shared__ u64 sA[2][64], sB[2][64], sC[2][64];
    const int tl = (t + 63) & 63;
    const int tr = (t + 1) & 63;

    sA[0][t] = x[14]; sB[0][t] = x[15]; sC[0][t] = x[0];
    __syncthreads();
    int pb = 0;

#pragma unroll 1
    for (int s = 0; s < 32; s++) {
        {   // stage 1: k1 from x
            u64 ym2 = sA[pb][tl], ym1 = sB[pb][tl], hp1 = sC[pb][tr];
#pragma unroll
            for (int i = 0; i < 16; i++) {
                u64 vc = x[i];
                u64 vp = (i < 15) ? x[i + 1] : hp1;
                u64 k  = fma2(fma2(ym2, NEG1, vp), ym1, fma2(vc, NEG1, F2));
                xa[i]  = fma2(k, H6, x[i]);
                y[i]   = fma2(k, H05, x[i]);
                ym2 = ym1; ym1 = vc;
            }
            pb ^= 1;
            sA[pb][t] = y[14]; sB[pb][t] = y[15]; sC[pb][t] = y[0];
            __syncthreads();
        }
        {   // stage 2: k2 from y
            u64 ym2 = sA[pb][tl], ym1 = sB[pb][tl], hp1 = sC[pb][tr];
#pragma unroll
            for (int i = 0; i < 16; i++) {
                u64 vc = y[i];
                u64 vp = (i < 15) ? y[i + 1] : hp1;
                u64 k  = fma2(fma2(ym2, NEG1, vp), ym1, fma2(vc, NEG1, F2));
                xa[i]  = fma2(k, H3, xa[i]);
                y[i]   = fma2(k, H05, x[i]);
                ym2 = ym1; ym1 = vc;
            }
            pb ^= 1;
            sA[pb][t] = y[14]; sB[pb][t] = y[15]; sC[pb][t] = y[0];
            __syncthreads();
        }
        {   // stage 3: k3 from y
            u64 ym2 = sA[pb][tl], ym1 = sB[pb][tl], hp1 = sC[pb][tr];
#pragma unroll
            for (int i = 0; i < 16; i++) {
                u64 vc = y[i];
                u64 vp = (i < 15) ? y[i + 1] : hp1;
                u64 k  = fma2(fma2(ym2, NEG1, vp), ym1, fma2(vc, NEG1, F2));
                xa[i]  = fma2(k, H3, xa[i]);
                y[i]   = fma2(k, H1, x[i]);
                ym2 = ym1; ym1 = vc;
            }
            pb ^= 1;
            sA[pb][t] = y[14]; sB[pb][t] = y[15]; sC[pb][t] = y[0];
            __syncthreads();
        }
        {   // stage 4: k4 from y; x = xa + h/6 k4
            u64 ym2 = sA[pb][tl], ym1 = sB[pb][tl], hp1 = sC[pb][tr];
#pragma unroll
            for (int i = 0; i < 16; i++) {
                u64 vc = y[i];
                u64 vp = (i < 15) ? y[i + 1] : hp1;
                u64 k  = fma2(fma2(ym2, NEG1, vp), ym1, fma2(vc, NEG1, F2));
                x[i]   = fma2(k, H6, xa[i]);
                ym2 = ym1; ym1 = vc;
            }
            pb ^= 1;
            sA[pb][t] = x[14]; sB[pb][t] = x[15]; sC[pb][t] = x[0];
            __syncthreads();
        }
    }

#pragma unroll
    for (int i = 0; i < 16; i++) {
        float2 v = unpack2(x[i]);
        p0[i] = v.x;
        p1[i] = v.y;
    }
}

// ---------------------------------------------------------------------------
// Kernel 3: logits = h @ W2^T + b2, log_softmax.
// ---------------------------------------------------------------------------
__global__ void __launch_bounds__(128) head_kernel(
    const float* __restrict__ W2, const float* __restrict__ b2,
    float* __restrict__ out)
{
    __shared__ float w2s[10 * 1024];
    __shared__ float b2s[10];
    const int tid = threadIdx.x;
    for (int i = tid; i < 10 * 1024; i += 128) w2s[i] = W2[i];
    if (tid < 10) b2s[tid] = b2[tid];
    __syncthreads();

    const int warp = tid >> 5;
    const int lane = tid & 31;
    const int row = blockIdx.x * 4 + warp;
    const float* hr = g_h + (size_t)row * 1024;

    float acc[10];
#pragma unroll
    for (int o = 0; o < 10; o++) acc[o] = 0.0f;

#pragma unroll 4
    for (int j = 0; j < 32; j++) {
        float hv = hr[lane + 32 * j];
#pragma unroll
        for (int o = 0; o < 10; o++)
            acc[o] = fmaf(hv, w2s[o * 1024 + lane + 32 * j], acc[o]);
    }
#pragma unroll
    for (int o = 0; o < 10; o++) {
#pragma unroll
        for (int off = 16; off > 0; off >>= 1)
            acc[o] += __shfl_xor_sync(0xFFFFFFFFu, acc[o], off);
    }
    float lg[10];
    float m = -1e30f;
#pragma unroll
    for (int o = 0; o < 10; o++) { lg[o] = acc[o] + b2s[o]; m = fmaxf(m, lg[o]); }
    float s = 0.0f;
#pragma unroll
    for (int o = 0; o < 10; o++) s += expf(lg[o] - m);
    float lse = logf(s) + m;
    if (lane < 10) out[(size_t)row * 10 + lane] = lg[lane] - lse;
}

// ---------------------------------------------------------------------------
extern "C" void kernel_launch(void* const* d_in, const int* in_sizes, int n_in,
                              void* d_out, int out_size)
{
    const float* x  = (const float*)d_in[0];  // [8192, 784]
    const float* W1 = (const float*)d_in[1];  // [1024, 784]
    const float* b1 = (const float*)d_in[2];  // [1024]
    const float* W2 = (const float*)d_in[3];  // [10, 1024]
    const float* b2 = (const float*)d_in[4];  // [10]
    float* out = (float*)d_out;               // [8192, 10]

    cudaFuncSetAttribute(gemm1_mma, cudaFuncAttributeMaxDynamicSharedMemorySize, GEMM_SMEM);

    dim3 g1(1024 / 128, 8192 / 128);          // (8, 64)
    gemm1_mma<<<g1, 256, GEMM_SMEM>>>(x, W1, b1);
    rk4_kernel<<<8192 / 2, 64>>>();
    head_kernel<<<8192 / 4, 128>>>(W2, b2, out);
}

// round 6
// speedup vs baseline: 3.2820x; 1.3950x over previous
#include <cuda_runtime.h>
#include <cstdint>

typedef unsigned long long u64;
typedef unsigned int u32;

// ===================== f32x2 helpers =====================
__device__ __forceinline__ u64 fma2(u64 a, u64 b, u64 c) {
    u64 d; asm("fma.rn.f32x2 %0, %1, %2, %3;" : "=l"(d) : "l"(a), "l"(b), "l"(c)); return d;
}
__device__ __forceinline__ u64 pack2(float lo, float hi) {
    u64 d; asm("mov.b64 %0, {%1, %2};" : "=l"(d) : "f"(lo), "f"(hi)); return d;
}
__device__ __forceinline__ float2 unpack2(u64 v) {
    float2 r; asm("mov.b64 {%0, %1}, %2;" : "=f"(r.x), "=f"(r.y) : "l"(v)); return r;
}

// Scratch hidden state h [8192 x 1024]
__device__ float g_h[8192 * 1024];

// ===================== mma.sync helpers =====================
__device__ __forceinline__ u32 smem_u32(const void* p) {
    u32 a;
    asm("{ .reg .u64 t; cvta.to.shared.u64 t, %1; cvt.u32.u64 %0, t; }" : "=r"(a) : "l"(p));
    return a;
}

#define LDSM4(r, addr) \
    asm volatile("ldmatrix.sync.aligned.m8n8.x4.shared.b16 {%0,%1,%2,%3}, [%4];" \
        : "=r"((r)[0]), "=r"((r)[1]), "=r"((r)[2]), "=r"((r)[3]) : "r"(addr))

#define MMA_BF16(c, a, b) \
    asm volatile("mma.sync.aligned.m16n8k16.row.col.f32.bf16.bf16.f32 " \
        "{%0,%1,%2,%3}, {%4,%5,%6,%7}, {%8,%9}, {%0,%1,%2,%3};" \
        : "+f"((c)[0]), "+f"((c)[1]), "+f"((c)[2]), "+f"((c)[3]) \
        : "r"((a)[0]), "r"((a)[1]), "r"((a)[2]), "r"((a)[3]), \
          "r"((b)[0]), "r"((b)[1]))

// split float pair -> bf16 hi-plane word + lo-plane word (lo16 = first elem)
__device__ __forceinline__ void split2(float x, float y, u32& hi, u32& lo) {
    u32 h;
    asm("cvt.rn.bf16x2.f32 %0, %1, %2;" : "=r"(h) : "f"(y), "f"(x));
    float hx = __uint_as_float(h << 16);
    float hy = __uint_as_float(h & 0xFFFF0000u);
    float lx = x - hx;
    float ly = y - hy;
    u32 l;
    asm("cvt.rn.bf16x2.f32 %0, %1, %2;" : "=r"(l) : "f"(ly), "f"(lx));
    hi = h; lo = l;
}

// smem geometry (rows x 40 ushort, 80B stride)
static constexpr int A_PLANE  = 256 * 40 * 2;   // 20480 B
static constexpr int B_PLANE  = 128 * 40 * 2;   // 10240 B
static constexpr int STAGE_B  = 2 * A_PLANE + 2 * B_PLANE;  // 61440
static constexpr int GEMM_SMEM = 2 * STAGE_B;   // 122880 dynamic

// ---------------------------------------------------------------------------
// Kernel 1: h = x @ W1^T + b1, bf16-split (3 products) mma.sync.
// CTA 256(M) x 128(N), BK=32 fp32, 8 warps (4x2), warp tile 64x64.
// A-frags register-resident per slice (reused over 8 n-frags); B streamed.
// ---------------------------------------------------------------------------
__global__ void __launch_bounds__(256) gemm1_mma(
    const float* __restrict__ A, const float* __restrict__ W,
    const float* __restrict__ bias)
{
    extern __shared__ __align__(16) char dsm[];
    const u32 sb = smem_u32(dsm);

    const int tid = threadIdx.x;
    const int wid = tid >> 5, lane = tid & 31;
    const int wm = wid >> 1;       // 0..3  (64-row band)
    const int wn = wid & 1;        // 0..1  (64-col band)
    const int bm = blockIdx.y * 256, bn = blockIdx.x * 128;

    // loaders: A row = tid (256 rows x 32 cols); B row = tid>>1 (128 x 32)
    const float* Ap = A + (size_t)(bm + tid) * 784;
    const int b_row = tid >> 1, b_cb = (tid & 1) * 16;
    const float* Wp = W + (size_t)(bn + b_row) * 784 + b_cb;

    float4 av[8], bv[4];
    auto LOAD = [&](int kt) {
        const int k0 = kt * 32;
#pragma unroll
        for (int j = 0; j < 8; j++) {
            int c = k0 + 4 * j;
            av[j] = (c < 784) ? *(const float4*)(Ap + c) : make_float4(0.f, 0.f, 0.f, 0.f);
        }
#pragma unroll
        for (int j = 0; j < 4; j++) {
            int c = k0 + b_cb + 4 * j;
            bv[j] = (c < 784) ? *(const float4*)(Wp + k0 + 4 * j) : make_float4(0.f, 0.f, 0.f, 0.f);
        }
    };
    auto STORE = [&](int s) {
        char* base = dsm + s * STAGE_B;
        unsigned short* pAh = (unsigned short*)(base);
        unsigned short* pAl = (unsigned short*)(base + A_PLANE);
        unsigned short* pBh = (unsigned short*)(base + 2 * A_PLANE);
        unsigned short* pBl = (unsigned short*)(base + 2 * A_PLANE + B_PLANE);
        const int offA = tid * 40;
#pragma unroll
        for (int j = 0; j < 8; j++) {
            u32 h01, l01, h23, l23;
            split2(av[j].x, av[j].y, h01, l01);
            split2(av[j].z, av[j].w, h23, l23);
            *(uint2*)&pAh[offA + 4 * j] = make_uint2(h01, h23);
            *(uint2*)&pAl[offA + 4 * j] = make_uint2(l01, l23);
        }
        const int offB = b_row * 40 + b_cb;
#pragma unroll
        for (int j = 0; j < 4; j++) {
            u32 h01, l01, h23, l23;
            split2(bv[j].x, bv[j].y, h01, l01);
            split2(bv[j].z, bv[j].w, h23, l23);
            *(uint2*)&pBh[offB + 4 * j] = make_uint2(h01, h23);
            *(uint2*)&pBl[offB + 4 * j] = make_uint2(l01, l23);
        }
    };

    float c[4][8][4];
#pragma unroll
    for (int mf = 0; mf < 4; mf++)
#pragma unroll
        for (int nf = 0; nf < 8; nf++)
#pragma unroll
            for (int r = 0; r < 4; r++) c[mf][nf][r] = 0.0f;

    // ldmatrix per-lane byte offsets within a plane
    const u32 a_lm = (u32)((wm * 64 + (lane & 15)) * 80 + (lane >> 4) * 16);
    const u32 b_lm = (u32)((wn * 64 + ((lane & 16) >> 1) + (lane & 7)) * 80 + ((lane >> 3) & 1) * 16);

    auto COMPUTE = [&](int s) {
        const u32 bufb = sb + s * STAGE_B;
#pragma unroll
        for (int ks = 0; ks < 2; ks++) {
            u32 ah[4][4], al[4][4];
            const u32 aoff = bufb + a_lm + ks * 32;
#pragma unroll
            for (int mf = 0; mf < 4; mf++) {
                LDSM4(ah[mf], aoff + mf * 1280);
                LDSM4(al[mf], aoff + A_PLANE + mf * 1280);
            }
            const u32 boff = bufb + 2 * A_PLANE + b_lm + ks * 32;
#pragma unroll
            for (int g = 0; g < 4; g++) {
                u32 th[4], tl[4];
                LDSM4(th, boff + g * 1280);
                LDSM4(tl, boff + B_PLANE + g * 1280);
                u32 bh0[2] = { th[0], th[1] }, bh1[2] = { th[2], th[3] };
                u32 bl0[2] = { tl[0], tl[1] }, bl1[2] = { tl[2], tl[3] };
#pragma unroll
                for (int mf = 0; mf < 4; mf++) {
                    MMA_BF16(c[mf][2 * g],     ah[mf], bh0);
                    MMA_BF16(c[mf][2 * g],     ah[mf], bl0);
                    MMA_BF16(c[mf][2 * g],     al[mf], bh0);
                    MMA_BF16(c[mf][2 * g + 1], ah[mf], bh1);
                    MMA_BF16(c[mf][2 * g + 1], ah[mf], bl1);
                    MMA_BF16(c[mf][2 * g + 1], al[mf], bh1);
                }
            }
        }
    };

    // prologue
    LOAD(0);
    STORE(0);
    LOAD(1);
    __syncthreads();

#pragma unroll 1
    for (int kt = 0; kt < 25; kt++) {
        const int s = kt & 1;
        if (kt < 24) {
            STORE(s ^ 1);            // tile kt+1 (staged in regs) -> other buffer
            if (kt < 23) LOAD(kt + 2);
        }
        COMPUTE(s);
        __syncthreads();
    }

    // epilogue: C + bias -> g_h
#pragma unroll
    for (int mf = 0; mf < 4; mf++) {
#pragma unroll
        for (int nf = 0; nf < 8; nf++) {
            const int row = bm + wm * 64 + mf * 16 + (lane >> 2);
            const int col = bn + wn * 64 + nf * 8 + (lane & 3) * 2;
            const float b0 = bias[col], b1 = bias[col + 1];
            float2 v0 = make_float2(c[mf][nf][0] + b0, c[mf][nf][1] + b1);
            float2 v1 = make_float2(c[mf][nf][2] + b0, c[mf][nf][3] + b1);
            *(float2*)(g_h + (size_t)row * 1024 + col) = v0;
            *(float2*)(g_h + (size_t)(row + 8) * 1024 + col) = v1;
        }
    }
}

// ---------------------------------------------------------------------------
// Kernel 2 (fused): RK4 Lorenz96 over [0,1] with h=1/20 (20 steps), then
// logits = h @ W2^T + b2 and log_softmax, all without writing h back.
// Block = 64 threads = one pair of batch rows packed into f32x2 lanes.
// ---------------------------------------------------------------------------
__global__ void __launch_bounds__(64) rk4_head_kernel(
    const float* __restrict__ W2, const float* __restrict__ b2,
    float* __restrict__ out)
{
    const int t = threadIdx.x;
    const int warp = t >> 5;
    const float* p0 = g_h + (size_t)(2 * blockIdx.x) * 1024 + t * 16;
    const float* p1 = p0 + 1024;

    const float hf = 1.0f / 20.0f;
    const u64 NEG1 = pack2(-1.0f, -1.0f);
    const u64 F2   = pack2(8.0f, 8.0f);
    const u64 H05  = pack2(hf * 0.5f, hf * 0.5f);
    const u64 H1   = pack2(hf, hf);
    const u64 H6   = pack2(hf / 6.0f, hf / 6.0f);
    const u64 H3   = pack2(hf / 3.0f, hf / 3.0f);

    u64 x[16], y[16], xa[16];
#pragma unroll
    for (int i = 0; i < 16; i++) x[i] = pack2(p0[i], p1[i]);

    __shared__ u64 sA[2][64], sB[2][64], sC[2][64];
    __shared__ float2 red[2][10];
    __shared__ float2 lg[10];
    __shared__ float lse2[2];

    const int tl = (t + 63) & 63;
    const int tr = (t + 1) & 63;

    sA[0][t] = x[14]; sB[0][t] = x[15]; sC[0][t] = x[0];
    __syncthreads();
    int pb = 0;

#pragma unroll 1
    for (int s = 0; s < 20; s++) {
        {   // stage 1: k1 from x
            u64 ym2 = sA[pb][tl], ym1 = sB[pb][tl], hp1 = sC[pb][tr];
#pragma unroll
            for (int i = 0; i < 16; i++) {
                u64 vc = x[i];
                u64 vp = (i < 15) ? x[i + 1] : hp1;
                u64 k  = fma2(fma2(ym2, NEG1, vp), ym1, fma2(vc, NEG1, F2));
                xa[i]  = fma2(k, H6, x[i]);
                y[i]   = fma2(k, H05, x[i]);
                ym2 = ym1; ym1 = vc;
            }
            pb ^= 1;
            sA[pb][t] = y[14]; sB[pb][t] = y[15]; sC[pb][t] = y[0];
            __syncthreads();
        }
        {   // stage 2: k2 from y
            u64 ym2 = sA[pb][tl], ym1 = sB[pb][tl], hp1 = sC[pb][tr];
#pragma unroll
            for (int i = 0; i < 16; i++) {
                u64 vc = y[i];
                u64 vp = (i < 15) ? y[i + 1] : hp1;
                u64 k  = fma2(fma2(ym2, NEG1, vp), ym1, fma2(vc, NEG1, F2));
                xa[i]  = fma2(k, H3, xa[i]);
                y[i]   = fma2(k, H05, x[i]);
                ym2 = ym1; ym1 = vc;
            }
            pb ^= 1;
            sA[pb][t] = y[14]; sB[pb][t] = y[15]; sC[pb][t] = y[0];
            __syncthreads();
        }
        {   // stage 3: k3 from y
            u64 ym2 = sA[pb][tl], ym1 = sB[pb][tl], hp1 = sC[pb][tr];
#pragma unroll
            for (int i = 0; i < 16; i++) {
                u64 vc = y[i];
                u64 vp = (i < 15) ? y[i + 1] : hp1;
                u64 k  = fma2(fma2(ym2, NEG1, vp), ym1, fma2(vc, NEG1, F2));
                xa[i]  = fma2(k, H3, xa[i]);
                y[i]   = fma2(k, H1, x[i]);
                ym2 = ym1; ym1 = vc;
            }
            pb ^= 1;
            sA[pb][t] = y[14]; sB[pb][t] = y[15]; sC[pb][t] = y[0];
            __syncthreads();
        }
        {   // stage 4: k4 from y; x = xa + h/6 k4
            u64 ym2 = sA[pb][tl], ym1 = sB[pb][tl], hp1 = sC[pb][tr];
#pragma unroll
            for (int i = 0; i < 16; i++) {
                u64 vc = y[i];
                u64 vp = (i < 15) ? y[i + 1] : hp1;
                u64 k  = fma2(fma2(ym2, NEG1, vp), ym1, fma2(vc, NEG1, F2));
                x[i]   = fma2(k, H6, xa[i]);
                ym2 = ym1; ym1 = vc;
            }
            pb ^= 1;
            sA[pb][t] = x[14]; sB[pb][t] = x[15]; sC[pb][t] = x[0];
            __syncthreads();
        }
    }

    // ---- fused head: logits + log_softmax ----
    float lx[10], ly[10];
#pragma unroll
    for (int o = 0; o < 10; o++) {
        const float4* w4 = (const float4*)(W2 + (size_t)o * 1024 + t * 16);
        u64 a = 0ull;
#pragma unroll
        for (int j = 0; j < 4; j++) {
            float4 w = w4[j];
            a = fma2(x[4 * j + 0], pack2(w.x, w.x), a);
            a = fma2(x[4 * j + 1], pack2(w.y, w.y), a);
            a = fma2(x[4 * j + 2], pack2(w.z, w.z), a);
            a = fma2(x[4 * j + 3], pack2(w.w, w.w), a);
        }
        float2 v = unpack2(a);
#pragma unroll
        for (int off = 16; off > 0; off >>= 1) {
            v.x += __shfl_xor_sync(0xFFFFFFFFu, v.x, off);
            v.y += __shfl_xor_sync(0xFFFFFFFFu, v.y, off);
        }
        lx[o] = v.x; ly[o] = v.y;
    }
    if ((t & 31) == 0) {
#pragma unroll
        for (int o = 0; o < 10; o++) red[warp][o] = make_float2(lx[o], ly[o]);
    }
    __syncthreads();
    if (t < 10) {
        float gx = red[0][t].x + red[1][t].x + b2[t];
        float gy = red[0][t].y + red[1][t].y + b2[t];
        lg[t] = make_float2(gx, gy);
    }
    __syncthreads();
    if (t < 2) {
        float m = -1e30f;
#pragma unroll
        for (int o = 0; o < 10; o++) {
            float v = (t == 0) ? lg[o].x : lg[o].y;
            m = fmaxf(m, v);
        }
        float sum = 0.0f;
#pragma unroll
        for (int o = 0; o < 10; o++) {
            float v = (t == 0) ? lg[o].x : lg[o].y;
            sum += expf(v - m);
        }
        lse2[t] = logf(sum) + m;
    }
    __syncthreads();
    if (t < 10) {
        out[(size_t)(2 * blockIdx.x) * 10 + t]     = lg[t].x - lse2[0];
        out[(size_t)(2 * blockIdx.x + 1) * 10 + t] = lg[t].y - lse2[1];
    }
}

// ---------------------------------------------------------------------------
extern "C" void kernel_launch(void* const* d_in, const int* in_sizes, int n_in,
                              void* d_out, int out_size)
{
    const float* x  = (const float*)d_in[0];  // [8192, 784]
    const float* W1 = (const float*)d_in[1];  // [1024, 784]
    const float* b1 = (const float*)d_in[2];  // [1024]
    const float* W2 = (const float*)d_in[3];  // [10, 1024]
    const float* b2 = (const float*)d_in[4];  // [10]
    float* out = (float*)d_out;               // [8192, 10]

    cudaFuncSetAttribute(gemm1_mma, cudaFuncAttributeMaxDynamicSharedMemorySize, GEMM_SMEM);

    dim3 g1(1024 / 128, 8192 / 256);          // (8, 32)
    gemm1_mma<<<g1, 256, GEMM_SMEM>>>(x, W1, b1);
    rk4_head_kernel<<<8192 / 2, 64>>>(W2, b2, out);
}